// round 13
// baseline (speedup 1.0000x reference)
#include <cuda_runtime.h>
#include <math.h>

#define N_NODES_MAX 50000
#define D 64
#define N_REL 8

__device__ float g_agg[(size_t)N_NODES_MAX * D];   // 12.8 MB
__device__ float g_cnt[N_NODES_MAX];
__device__ float g_w[N_REL * 2 * D];               // w = W_r.sum(-1)
__device__ float g_y[(size_t)N_NODES_MAX * 16];    // y tables
__device__ float g_part[(size_t)N_NODES_MAX * D];  // partial out = bias + x@Wx

// ---------------------------------------------------------------------------
// Kernel 1: w[r][j] = sum_k W_r[r][j][k]
// ---------------------------------------------------------------------------
__global__ void wsum_kernel(const float* __restrict__ W_r) {
    int r = blockIdx.x;
    int j = threadIdx.x;
    const float4* row = (const float4*)(W_r + ((size_t)r * 2 * D + j) * D);
    float4 s = make_float4(0.f, 0.f, 0.f, 0.f);
#pragma unroll
    for (int k = 0; k < D / 4; k++) {
        float4 v = __ldg(row + k);
        s.x += v.x; s.y += v.y; s.z += v.z; s.w += v.w;
    }
    g_w[r * 2 * D + j] = (s.x + s.y) + (s.z + s.w);
}

// ---------------------------------------------------------------------------
// Kernel 1b: y tables + fused scratch zeroing.
// ---------------------------------------------------------------------------
__global__ __launch_bounds__(256) void y_kernel(const float* __restrict__ x, int N) {
    __shared__ float xt[D][17];
    __shared__ float wt[D][16];

    int tid = threadIdx.x;
    int base = blockIdx.x * 16;

    {
        int gidx = blockIdx.x * blockDim.x + tid;
        int n_agg4 = N * (D / 4);
        int stride = gridDim.x * blockDim.x;
        for (int i = gidx; i < n_agg4; i += stride)
            ((float4*)g_agg)[i] = make_float4(0.f, 0.f, 0.f, 0.f);
        for (int i = gidx; i < N; i += stride)
            g_cnt[i] = 0.f;
    }

#pragma unroll
    for (int q = 0; q < 4; q++) {
        int idx = tid + q * 256;
        int k = idx >> 4, j = idx & 15;
        wt[k][j] = (j < 8) ? g_w[j * 2 * D + k] : g_w[(j - 8) * 2 * D + D + k];
    }
    {
        int n = tid >> 4;
        int k0 = (tid & 15) * 4;
        int nn = min(base + n, N - 1);
        float4 v = __ldg((const float4*)(x + (size_t)nn * D + k0));
        xt[k0 + 0][n] = v.x; xt[k0 + 1][n] = v.y;
        xt[k0 + 2][n] = v.z; xt[k0 + 3][n] = v.w;
    }
    __syncthreads();

    int n = tid & 15, j = tid >> 4;
    float acc = 0.f;
#pragma unroll
    for (int k = 0; k < D; k++) acc += xt[k][n] * wt[k][j];

    int nn = base + n;
    if (nn < N) g_y[(size_t)nn * 16 + j] = acc;
}

// ---------------------------------------------------------------------------
// FUSED kernel: edge phase + nodeA (x-half GEMM), block-role split.
//   blockIdx % 3 < 2  -> edge role (one edge per lane, shfl-broadcast + RED)
//   blockIdx % 3 == 2 -> nodeA role: out_part[n][32 outs] = bias + x[n]@Wx
// Interleaved roles keep LTS (edge) and FMA (nodeA) loaded simultaneously.
// ---------------------------------------------------------------------------
__global__ __launch_bounds__(256, 4) void fused_edge_nodeA_kernel(
        const float* __restrict__ x,
        const int* __restrict__ src,
        const int* __restrict__ dst,
        const int* __restrict__ rel,
        const float* __restrict__ Wl,   // [64][128]
        const float* __restrict__ b,    // [64]
        int E, int N) {
    __shared__ float csm[D][66];        // 16.9 KB (nodeA)
    __shared__ float wsmA[32][D];       // 8 KB    (nodeA)

    int bid = blockIdx.x;
    int tid = threadIdx.x;
    int role = bid % 3;

    if (role < 2) {
        // ================= EDGE ROLE =================
        int eb = (bid / 3) * 2 + role;          // edge block index
        int gw = eb * 8 + (tid >> 5);           // global warp
        int lane = tid & 31;

        int ew = gw * 32;
        if (ew >= E) return;
        int ne = min(32, E - ew);

        int e = ew + min(lane, ne - 1);
        int s = __ldg(src + e);
        int d = __ldg(dst + e);
        int r = __ldg(rel + e);

        float yd = __ldg(g_y + (size_t)d * 16 + r);
        float ys = __ldg(g_y + (size_t)s * 16 + 8 + r);
        float gate = 1.0f / (1.0f + __expf(-(yd + ys)));

        if (lane < ne) atomicAdd(g_cnt + d, 1.0f);

        const float2* x2 = (const float2*)x;
        int j = 0;
        for (; j + 4 <= ne; j += 4) {
            int s0 = __shfl_sync(0xffffffffu, s, j + 0);
            int s1 = __shfl_sync(0xffffffffu, s, j + 1);
            int s2 = __shfl_sync(0xffffffffu, s, j + 2);
            int s3 = __shfl_sync(0xffffffffu, s, j + 3);
            int d0 = __shfl_sync(0xffffffffu, d, j + 0);
            int d1 = __shfl_sync(0xffffffffu, d, j + 1);
            int d2 = __shfl_sync(0xffffffffu, d, j + 2);
            int d3 = __shfl_sync(0xffffffffu, d, j + 3);
            float g0 = __shfl_sync(0xffffffffu, gate, j + 0);
            float g1 = __shfl_sync(0xffffffffu, gate, j + 1);
            float g2 = __shfl_sync(0xffffffffu, gate, j + 2);
            float g3 = __shfl_sync(0xffffffffu, gate, j + 3);

            float2 v0 = __ldg(x2 + (size_t)s0 * (D / 2) + lane);
            float2 v1 = __ldg(x2 + (size_t)s1 * (D / 2) + lane);
            float2 v2 = __ldg(x2 + (size_t)s2 * (D / 2) + lane);
            float2 v3 = __ldg(x2 + (size_t)s3 * (D / 2) + lane);

            float* a0 = g_agg + (size_t)d0 * D + lane * 2;
            float* a1 = g_agg + (size_t)d1 * D + lane * 2;
            float* a2 = g_agg + (size_t)d2 * D + lane * 2;
            float* a3 = g_agg + (size_t)d3 * D + lane * 2;
            asm volatile("red.global.add.v2.f32 [%0], {%1,%2};"
                         :: "l"(a0), "f"(v0.x * g0), "f"(v0.y * g0) : "memory");
            asm volatile("red.global.add.v2.f32 [%0], {%1,%2};"
                         :: "l"(a1), "f"(v1.x * g1), "f"(v1.y * g1) : "memory");
            asm volatile("red.global.add.v2.f32 [%0], {%1,%2};"
                         :: "l"(a2), "f"(v2.x * g2), "f"(v2.y * g2) : "memory");
            asm volatile("red.global.add.v2.f32 [%0], {%1,%2};"
                         :: "l"(a3), "f"(v3.x * g3), "f"(v3.y * g3) : "memory");
        }
        for (; j < ne; j++) {
            int sj = __shfl_sync(0xffffffffu, s, j);
            int dj = __shfl_sync(0xffffffffu, d, j);
            float gj = __shfl_sync(0xffffffffu, gate, j);
            float2 v = __ldg(x2 + (size_t)sj * (D / 2) + lane);
            float* a = g_agg + (size_t)dj * D + lane * 2;
            asm volatile("red.global.add.v2.f32 [%0], {%1,%2};"
                         :: "l"(a), "f"(v.x * gj), "f"(v.y * gj) : "memory");
        }
    } else {
        // ================= NODEA ROLE =================
        // tile: 64 nodes x 32 outs. nb selects node tile + out half.
        int nb = bid / 3;
        int ntile = nb >> 1;
        int ohalf = (nb & 1) * 32;
        int base = ntile * 64;
        if (base >= N) return;

        int tx = tid & 31;    // node pair
        int ty = tid >> 5;    // out group of 4 (within the 32-out half)
        int obase = ohalf + ty * 4;

        // stage Wx chunk: wsmA[o][k] = Wl[ohalf+o][k], k<64
#pragma unroll
        for (int q = 0; q < 2; q++) {
            int idx = (tid + q * 256) * 4;   // 0..4092
            int o = idx >> 6, k = idx & 63;
            float4 v = __ldg((const float4*)(Wl + (size_t)(ohalf + o) * 2 * D + k));
            *(float4*)&wsmA[o][k] = v;
        }
        // stage x chunk transposed: csm[k][n]
        {
            int n = tid & 63;
            int k0 = (tid >> 6) * 16;
            int nn = min(base + n, N - 1);
            const float4* srcp = (const float4*)(x + (size_t)nn * D + k0);
#pragma unroll
            for (int q = 0; q < 4; q++) {
                float4 v = __ldg(srcp + q);
                int k = k0 + q * 4;
                csm[k + 0][n] = v.x;
                csm[k + 1][n] = v.y;
                csm[k + 2][n] = v.z;
                csm[k + 3][n] = v.w;
            }
        }
        __syncthreads();

        float acc[2][4];
#pragma unroll
        for (int j = 0; j < 4; j++) {
            float bv = __ldg(b + obase + j);
            acc[0][j] = bv; acc[1][j] = bv;
        }

#pragma unroll 8
        for (int k4 = 0; k4 < D; k4 += 4) {
            float4 w[4];
#pragma unroll
            for (int j = 0; j < 4; j++)
                w[j] = *(const float4*)&wsmA[ty * 4 + j][k4];   // broadcast

            float2 c0 = *(const float2*)&csm[k4 + 0][tx * 2];
            float2 c1 = *(const float2*)&csm[k4 + 1][tx * 2];
            float2 c2 = *(const float2*)&csm[k4 + 2][tx * 2];
            float2 c3 = *(const float2*)&csm[k4 + 3][tx * 2];

#pragma unroll
            for (int j = 0; j < 4; j++) {
                acc[0][j] += c0.x * w[j].x; acc[1][j] += c0.y * w[j].x;
                acc[0][j] += c1.x * w[j].y; acc[1][j] += c1.y * w[j].y;
                acc[0][j] += c2.x * w[j].z; acc[1][j] += c2.y * w[j].z;
                acc[0][j] += c3.x * w[j].w; acc[1][j] += c3.y * w[j].w;
            }
        }

#pragma unroll
        for (int i = 0; i < 2; i++) {
            int n = base + tx * 2 + i;
            if (n < N) {
                *(float4*)(g_part + (size_t)n * D + obase) =
                    make_float4(acc[i][0], acc[i][1], acc[i][2], acc[i][3]);
            }
        }
    }
}

// ---------------------------------------------------------------------------
// nodeB: out = leaky_relu(part + (agg/max(cnt,1)) @ Wagg^T)
//   Block: 256 threads, 64 nodes x 64 outs; thread 2n x 8o (R10 structure).
// ---------------------------------------------------------------------------
__global__ __launch_bounds__(256, 3) void nodeB_kernel(
        const float* __restrict__ Wl,   // [64][128]
        float* __restrict__ out,
        int N) {
    __shared__ float csm[D][66];
    __shared__ float wsm[D][D];

    int tid = threadIdx.x;
    int tx = tid & 31;
    int ty = tid >> 5;
    int base = blockIdx.x * 64;

    // stage Wagg chunk: wsm[o][k] = Wl[o][64+k]
#pragma unroll
    for (int q = 0; q < 4; q++) {
        int idx = (tid + q * 256) * 4;
        int o = idx >> 6, k = idx & 63;
        float4 v = __ldg((const float4*)(Wl + (size_t)o * 2 * D + D + k));
        *(float4*)&wsm[o][k] = v;
    }
    // stage agg chunk transposed w/ scale
    {
        int n = tid & 63;
        int k0 = (tid >> 6) * 16;
        int nn = min(base + n, N - 1);
        float scale = 1.0f / fmaxf(g_cnt[nn], 1.0f);
        const float4* srcp = (const float4*)(g_agg + (size_t)nn * D + k0);
#pragma unroll
        for (int q = 0; q < 4; q++) {
            float4 v = __ldg(srcp + q);
            int k = k0 + q * 4;
            csm[k + 0][n] = v.x * scale;
            csm[k + 1][n] = v.y * scale;
            csm[k + 2][n] = v.z * scale;
            csm[k + 3][n] = v.w * scale;
        }
    }
    __syncthreads();

    // acc init from partial
    float acc[2][8];
#pragma unroll
    for (int i = 0; i < 2; i++) {
        int nn = min(base + tx * 2 + i, N - 1);
        float4 p0 = *(const float4*)(g_part + (size_t)nn * D + ty * 8);
        float4 p1 = *(const float4*)(g_part + (size_t)nn * D + ty * 8 + 4);
        acc[i][0] = p0.x; acc[i][1] = p0.y; acc[i][2] = p0.z; acc[i][3] = p0.w;
        acc[i][4] = p1.x; acc[i][5] = p1.y; acc[i][6] = p1.z; acc[i][7] = p1.w;
    }

#pragma unroll 8
    for (int k4 = 0; k4 < D; k4 += 4) {
        float4 w[8];
#pragma unroll
        for (int j = 0; j < 8; j++)
            w[j] = *(const float4*)&wsm[ty * 8 + j][k4];   // broadcast

        float2 c0 = *(const float2*)&csm[k4 + 0][tx * 2];
        float2 c1 = *(const float2*)&csm[k4 + 1][tx * 2];
        float2 c2 = *(const float2*)&csm[k4 + 2][tx * 2];
        float2 c3 = *(const float2*)&csm[k4 + 3][tx * 2];

#pragma unroll
        for (int j = 0; j < 8; j++) {
            acc[0][j] += c0.x * w[j].x; acc[1][j] += c0.y * w[j].x;
            acc[0][j] += c1.x * w[j].y; acc[1][j] += c1.y * w[j].y;
            acc[0][j] += c2.x * w[j].z; acc[1][j] += c2.y * w[j].z;
            acc[0][j] += c3.x * w[j].w; acc[1][j] += c3.y * w[j].w;
        }
    }

#pragma unroll
    for (int i = 0; i < 2; i++) {
        int n = base + tx * 2 + i;
        if (n < N) {
            float* op = out + (size_t)n * D + ty * 8;
            float4 r0, r1;
            r0.x = acc[i][0] > 0.f ? acc[i][0] : 0.01f * acc[i][0];
            r0.y = acc[i][1] > 0.f ? acc[i][1] : 0.01f * acc[i][1];
            r0.z = acc[i][2] > 0.f ? acc[i][2] : 0.01f * acc[i][2];
            r0.w = acc[i][3] > 0.f ? acc[i][3] : 0.01f * acc[i][3];
            r1.x = acc[i][4] > 0.f ? acc[i][4] : 0.01f * acc[i][4];
            r1.y = acc[i][5] > 0.f ? acc[i][5] : 0.01f * acc[i][5];
            r1.z = acc[i][6] > 0.f ? acc[i][6] : 0.01f * acc[i][6];
            r1.w = acc[i][7] > 0.f ? acc[i][7] : 0.01f * acc[i][7];
            *(float4*)op = r0;
            *(float4*)(op + 4) = r1;
        }
    }
}

// ---------------------------------------------------------------------------
extern "C" void kernel_launch(void* const* d_in, const int* in_sizes, int n_in,
                              void* d_out, int out_size) {
    const float* x    = (const float*)d_in[0];
    const int*   src  = (const int*)d_in[1];
    const int*   dst  = (const int*)d_in[2];
    const int*   rel  = (const int*)d_in[3];
    const float* W_r  = (const float*)d_in[4];
    const float* W_lin= (const float*)d_in[5];
    const float* b_lin= (const float*)d_in[6];
    float* out = (float*)d_out;

    int N = in_sizes[0] / D;     // 50000
    int E = in_sizes[1];         // 800000

    wsum_kernel<<<N_REL, 2 * D>>>(W_r);

    y_kernel<<<(N + 15) / 16, 256>>>(x, N);

    // fused edge + nodeA: grid = 3 * max(edge_pairs, nodeA_tiles)
    int edge_blocks = (E + 255) / 256;              // 3125 (256 edges/block)
    int nodeA_tiles = ((N + 63) / 64) * 2;          // 1564
    int third = max((edge_blocks + 1) / 2, nodeA_tiles);
    fused_edge_nodeA_kernel<<<third * 3, 256>>>(x, src, dst, rel, W_lin, b_lin, E, N);

    nodeB_kernel<<<(N + 63) / 64, 256>>>(W_lin, out, N);
}

// round 14
// speedup vs baseline: 1.0561x; 1.0561x over previous
#include <cuda_runtime.h>
#include <math.h>

#define N_NODES_MAX 50000
#define D 64
#define N_REL 8

__device__ float g_agg[(size_t)N_NODES_MAX * D];   // 12.8 MB
__device__ float g_cnt[N_NODES_MAX];
__device__ float g_w[N_REL * 2 * D];               // w = W_r.sum(-1)
__device__ float g_y[(size_t)N_NODES_MAX * 16];    // y tables

// ---------------------------------------------------------------------------
// Kernel 1: w[r][j] = sum_k W_r[r][j][k]
// ---------------------------------------------------------------------------
__global__ void wsum_kernel(const float* __restrict__ W_r) {
    int r = blockIdx.x;
    int j = threadIdx.x;
    const float4* row = (const float4*)(W_r + ((size_t)r * 2 * D + j) * D);
    float4 s = make_float4(0.f, 0.f, 0.f, 0.f);
#pragma unroll
    for (int k = 0; k < D / 4; k++) {
        float4 v = __ldg(row + k);
        s.x += v.x; s.y += v.y; s.z += v.z; s.w += v.w;
    }
    g_w[r * 2 * D + j] = (s.x + s.y) + (s.z + s.w);
}

// ---------------------------------------------------------------------------
// Kernel 1b: y tables + fused scratch zeroing.
// ---------------------------------------------------------------------------
__global__ __launch_bounds__(256) void y_kernel(const float* __restrict__ x, int N) {
    __shared__ float xt[D][17];
    __shared__ float wt[D][16];

    int tid = threadIdx.x;
    int base = blockIdx.x * 16;

    {
        int gidx = blockIdx.x * blockDim.x + tid;
        int n_agg4 = N * (D / 4);
        int stride = gridDim.x * blockDim.x;
        for (int i = gidx; i < n_agg4; i += stride)
            ((float4*)g_agg)[i] = make_float4(0.f, 0.f, 0.f, 0.f);
        for (int i = gidx; i < N; i += stride)
            g_cnt[i] = 0.f;
    }

#pragma unroll
    for (int q = 0; q < 4; q++) {
        int idx = tid + q * 256;
        int k = idx >> 4, j = idx & 15;
        wt[k][j] = (j < 8) ? g_w[j * 2 * D + k] : g_w[(j - 8) * 2 * D + D + k];
    }
    {
        int n = tid >> 4;
        int k0 = (tid & 15) * 4;
        int nn = min(base + n, N - 1);
        float4 v = __ldg((const float4*)(x + (size_t)nn * D + k0));
        xt[k0 + 0][n] = v.x; xt[k0 + 1][n] = v.y;
        xt[k0 + 2][n] = v.z; xt[k0 + 3][n] = v.w;
    }
    __syncthreads();

    int n = tid & 15, j = tid >> 4;
    float acc = 0.f;
#pragma unroll
    for (int k = 0; k < D; k++) acc += xt[k][n] * wt[k][j];

    int nn = base + n;
    if (nn < N) g_y[(size_t)nn * 16 + j] = acc;
}

// ---------------------------------------------------------------------------
// Kernel 3: edge phase v4.
//   Scalar phase: one edge per lane (coalesced idx/y loads, 1 sigmoid/edge,
//   cnt RED per lane).
//   Vector phase: half-warp per edge, float4 per lane; two edges in flight
//   per warp (half 0 -> edges 0..15, half 1 -> edges 16..31). 16 LDG.128 +
//   16 RED.128 per warp (2x fewer LSU ops than the v2 form, same bytes).
// ---------------------------------------------------------------------------
__global__ __launch_bounds__(256) void edge_kernel(
        const float* __restrict__ x,
        const int* __restrict__ src,
        const int* __restrict__ dst,
        const int* __restrict__ rel,
        int E) {
    int warp = (blockIdx.x * blockDim.x + threadIdx.x) >> 5;
    int lane = threadIdx.x & 31;

    int ew = warp * 32;
    if (ew >= E) return;
    int ne = min(32, E - ew);

    // ---- scalar phase ----
    int e = ew + min(lane, ne - 1);
    int s = __ldg(src + e);
    int d = __ldg(dst + e);
    int r = __ldg(rel + e);

    float yd = __ldg(g_y + (size_t)d * 16 + r);
    float ys = __ldg(g_y + (size_t)s * 16 + 8 + r);
    float gate = 1.0f / (1.0f + __expf(-(yd + ys)));

    if (lane < ne) atomicAdd(g_cnt + d, 1.0f);

    // ---- vector phase ----
    int half = lane >> 4;
    int sub  = lane & 15;
    const float4* x4 = (const float4*)x;

#pragma unroll 4
    for (int jj = 0; jj < 16; jj++) {
        int sl = half * 16 + jj;                       // edge index within warp
        int sj = __shfl_sync(0xffffffffu, s, sl);
        int dj = __shfl_sync(0xffffffffu, d, sl);
        float gj = __shfl_sync(0xffffffffu, gate, sl);
        if (sl < ne) {
            float4 v = __ldg(x4 + (size_t)sj * (D / 4) + sub);
            float* a = g_agg + (size_t)dj * D + sub * 4;
            asm volatile("red.global.add.v4.f32 [%0], {%1,%2,%3,%4};"
                         :: "l"(a), "f"(v.x * gj), "f"(v.y * gj),
                            "f"(v.z * gj), "f"(v.w * gj)
                         : "memory");
        }
    }
}

// ---------------------------------------------------------------------------
// Kernel 4: node GEMM. Same tiling as R10 (64n x 64o, thread 2n x 8o) but the
// inner j-loop is split into two groups of 4 to halve live weight registers
// (~60 regs), enabling 4 blocks/SM via __launch_bounds__(256,4).
// ---------------------------------------------------------------------------
#define BN 64
#define KCH 64

__global__ __launch_bounds__(256, 4) void node_kernel(
        const float* __restrict__ x,
        const float* __restrict__ Wl,   // [64][128]
        const float* __restrict__ b,    // [64]
        float* __restrict__ out,
        int N) {
    __shared__ float csm[KCH][66];      // 16.9 KB
    __shared__ float wsm[D][KCH];       // 16 KB

    int tid = threadIdx.x;
    int tx = tid & 31;
    int ty = tid >> 5;
    int base = blockIdx.x * BN;

    float acc[2][8];
#pragma unroll
    for (int j = 0; j < 8; j++) {
        float bv = __ldg(b + ty * 8 + j);
        acc[0][j] = bv; acc[1][j] = bv;
    }

#pragma unroll
    for (int kc = 0; kc < 2; kc++) {
        // stage weight chunk: wsm[o][k] = Wl[o][kc*64 + k]
#pragma unroll
        for (int q = 0; q < 4; q++) {
            int idx = (tid + q * 256) * 4;
            int o = idx >> 6, k = idx & 63;
            float4 v = __ldg((const float4*)(Wl + (size_t)o * 2 * D + kc * KCH + k));
            *(float4*)&wsm[o][k] = v;
        }
        // stage combined chunk transposed: csm[k][node]
        {
            int n = tid & 63;
            int q16 = tid >> 6;
            int k0 = q16 * 16;
            int nn = min(base + n, N - 1);
            const float4* srcp;
            float scale;
            if (kc == 0) {
                srcp = (const float4*)(x + (size_t)nn * D + k0);
                scale = 1.0f;
            } else {
                srcp = (const float4*)(g_agg + (size_t)nn * D + k0);
                scale = 1.0f / fmaxf(g_cnt[nn], 1.0f);
            }
#pragma unroll
            for (int q = 0; q < 4; q++) {
                float4 v = __ldg(srcp + q);
                int k = k0 + q * 4;
                csm[k + 0][n] = v.x * scale;
                csm[k + 1][n] = v.y * scale;
                csm[k + 2][n] = v.z * scale;
                csm[k + 3][n] = v.w * scale;
            }
        }
        __syncthreads();

#pragma unroll 4
        for (int k4 = 0; k4 < KCH; k4 += 4) {
            float2 c0 = *(const float2*)&csm[k4 + 0][tx * 2];
            float2 c1 = *(const float2*)&csm[k4 + 1][tx * 2];
            float2 c2 = *(const float2*)&csm[k4 + 2][tx * 2];
            float2 c3 = *(const float2*)&csm[k4 + 3][tx * 2];

            // group A: outputs 0..3 (4 live w regs of float4)
            {
                float4 w0 = *(const float4*)&wsm[ty * 8 + 0][k4];
                float4 w1 = *(const float4*)&wsm[ty * 8 + 1][k4];
                float4 w2 = *(const float4*)&wsm[ty * 8 + 2][k4];
                float4 w3 = *(const float4*)&wsm[ty * 8 + 3][k4];
                acc[0][0] += c0.x * w0.x + c1.x * w0.y + c2.x * w0.z + c3.x * w0.w;
                acc[1][0] += c0.y * w0.x + c1.y * w0.y + c2.y * w0.z + c3.y * w0.w;
                acc[0][1] += c0.x * w1.x + c1.x * w1.y + c2.x * w1.z + c3.x * w1.w;
                acc[1][1] += c0.y * w1.x + c1.y * w1.y + c2.y * w1.z + c3.y * w1.w;
                acc[0][2] += c0.x * w2.x + c1.x * w2.y + c2.x * w2.z + c3.x * w2.w;
                acc[1][2] += c0.y * w2.x + c1.y * w2.y + c2.y * w2.z + c3.y * w2.w;
                acc[0][3] += c0.x * w3.x + c1.x * w3.y + c2.x * w3.z + c3.x * w3.w;
                acc[1][3] += c0.y * w3.x + c1.y * w3.y + c2.y * w3.z + c3.y * w3.w;
            }
            // group B: outputs 4..7
            {
                float4 w0 = *(const float4*)&wsm[ty * 8 + 4][k4];
                float4 w1 = *(const float4*)&wsm[ty * 8 + 5][k4];
                float4 w2 = *(const float4*)&wsm[ty * 8 + 6][k4];
                float4 w3 = *(const float4*)&wsm[ty * 8 + 7][k4];
                acc[0][4] += c0.x * w0.x + c1.x * w0.y + c2.x * w0.z + c3.x * w0.w;
                acc[1][4] += c0.y * w0.x + c1.y * w0.y + c2.y * w0.z + c3.y * w0.w;
                acc[0][5] += c0.x * w1.x + c1.x * w1.y + c2.x * w1.z + c3.x * w1.w;
                acc[1][5] += c0.y * w1.x + c1.y * w1.y + c2.y * w1.z + c3.y * w1.w;
                acc[0][6] += c0.x * w2.x + c1.x * w2.y + c2.x * w2.z + c3.x * w2.w;
                acc[1][6] += c0.y * w2.x + c1.y * w2.y + c2.y * w2.z + c3.y * w2.w;
                acc[0][7] += c0.x * w3.x + c1.x * w3.y + c2.x * w3.z + c3.x * w3.w;
                acc[1][7] += c0.y * w3.x + c1.y * w3.y + c2.y * w3.z + c3.y * w3.w;
            }
        }
        __syncthreads();
    }

#pragma unroll
    for (int i = 0; i < 2; i++) {
        int n = base + tx * 2 + i;
        if (n < N) {
            float* op = out + (size_t)n * D + ty * 8;
            float4 r0, r1;
            r0.x = acc[i][0] > 0.f ? acc[i][0] : 0.01f * acc[i][0];
            r0.y = acc[i][1] > 0.f ? acc[i][1] : 0.01f * acc[i][1];
            r0.z = acc[i][2] > 0.f ? acc[i][2] : 0.01f * acc[i][2];
            r0.w = acc[i][3] > 0.f ? acc[i][3] : 0.01f * acc[i][3];
            r1.x = acc[i][4] > 0.f ? acc[i][4] : 0.01f * acc[i][4];
            r1.y = acc[i][5] > 0.f ? acc[i][5] : 0.01f * acc[i][5];
            r1.z = acc[i][6] > 0.f ? acc[i][6] : 0.01f * acc[i][6];
            r1.w = acc[i][7] > 0.f ? acc[i][7] : 0.01f * acc[i][7];
            *(float4*)op = r0;
            *(float4*)(op + 4) = r1;
        }
    }
}

// ---------------------------------------------------------------------------
extern "C" void kernel_launch(void* const* d_in, const int* in_sizes, int n_in,
                              void* d_out, int out_size) {
    const float* x    = (const float*)d_in[0];
    const int*   src  = (const int*)d_in[1];
    const int*   dst  = (const int*)d_in[2];
    const int*   rel  = (const int*)d_in[3];
    const float* W_r  = (const float*)d_in[4];
    const float* W_lin= (const float*)d_in[5];
    const float* b_lin= (const float*)d_in[6];
    float* out = (float*)d_out;

    int N = in_sizes[0] / D;     // 50000
    int E = in_sizes[1];         // 800000

    wsum_kernel<<<N_REL, 2 * D>>>(W_r);

    y_kernel<<<(N + 15) / 16, 256>>>(x, N);

    int ewarps = (E + 31) / 32;
    edge_kernel<<<(ewarps * 32 + 255) / 256, 256>>>(x, src, dst, rel, E);

    node_kernel<<<(N + BN - 1) / BN, 256>>>(x, W_lin, b_lin, out, N);
}